// round 3
// baseline (speedup 1.0000x reference)
#include <cuda_runtime.h>
#include <cuda_fp16.h>
#include <cstdint>

#define NP 4096
#define DI 128
#define REGINV 20.0f          // 1/0.05
#define MUV (1.0f/4096.0f)
#define EPSV 1e-8f
#define NITER 100

// ---------------- device scratch (no allocations allowed) ----------------
__device__ __half g_K [(size_t)NP * NP];   // 32 MB  K[i][j]
__device__ __half g_KT[(size_t)NP * NP];   // 32 MB  K[j][i] (row-major transpose)
__device__ __half g_C [(size_t)NP * NP];   // 32 MB  clipped cost
__device__ float  g_u[NP];
__device__ float  g_v[NP];
__device__ float  g_norm[3][NP];           // row sq-norms of z0,z1,z2
__device__ float  g_part[512];
__device__ float  g_result;

__device__ __forceinline__ float wsum(float v) {
#pragma unroll
    for (int o = 16; o > 0; o >>= 1) v += __shfl_down_sync(0xffffffffu, v, o);
    return v;
}

// ---------------- row squared norms of all three inputs (+ zero g_result) --
__global__ void norms_k(const float* __restrict__ z0, const float* __restrict__ z1,
                        const float* __restrict__ z2) {
    if (blockIdx.x == 0 && threadIdx.x == 0) g_result = 0.f;
    int w    = (blockIdx.x * blockDim.x + threadIdx.x) >> 5;   // global warp = row id
    int lane = threadIdx.x & 31;
    if (w >= 3 * NP) return;
    const float* z = (w < NP) ? z0 : (w < 2 * NP ? z1 : z2);
    int r = w & (NP - 1);
    float4 f = *(const float4*)(z + (size_t)r * DI + lane * 4);
    float s = f.x * f.x + f.y * f.y + f.z * f.z + f.w * f.w;
    s = wsum(s);
    if (lane == 0) ((float*)g_norm)[w] = s;
}

// ---------------- K = exp(-clip(C,0)/reg) fp16, + transpose, + C fp16 ------
__global__ void gemm_expK_k(const float* __restrict__ X, const float* __restrict__ Y,
                            int nxi, int nyi) {
    __shared__ float xs[32][65];
    __shared__ float ys[32][65];
    __shared__ alignas(8) __half tr[64][68];

    const float* nx = g_norm[nxi];
    const float* ny = g_norm[nyi];

    int tid = threadIdx.x;
    int tx = tid & 15, ty = tid >> 4;
    int i0 = (blockIdx.x >> 6) << 6;
    int j0 = (blockIdx.x & 63) << 6;

    float acc[4][4];
#pragma unroll
    for (int a = 0; a < 4; a++)
#pragma unroll
        for (int b = 0; b < 4; b++) acc[a][b] = 0.f;

    for (int kk = 0; kk < DI; kk += 32) {
        __syncthreads();
#pragma unroll
        for (int idx = tid; idx < 2048; idx += 256) {
            int r = idx >> 5, k = idx & 31;
            xs[k][r] = X[(size_t)(i0 + r) * DI + kk + k];
            ys[k][r] = Y[(size_t)(j0 + r) * DI + kk + k];
        }
        __syncthreads();
#pragma unroll
        for (int k = 0; k < 32; k++) {
            float xr[4], yr[4];
#pragma unroll
            for (int a = 0; a < 4; a++) xr[a] = xs[k][ty * 4 + a];
#pragma unroll
            for (int b = 0; b < 4; b++) yr[b] = ys[k][tx * 4 + b];
#pragma unroll
            for (int a = 0; a < 4; a++)
#pragma unroll
                for (int b = 0; b < 4; b++) acc[a][b] += xr[a] * yr[b];
        }
    }

    // epilogue: write K and C coalesced (8B/thread), stage transpose in smem
#pragma unroll
    for (int a = 0; a < 4; a++) {
        int i = i0 + ty * 4 + a;
        float ni = nx[i];
        alignas(8) __half hk[4];
        alignas(8) __half hc[4];
#pragma unroll
        for (int b = 0; b < 4; b++) {
            int j = j0 + tx * 4 + b;
            float c  = fmaxf(ni + ny[j] - 2.0f * acc[a][b], 0.0f);
            float kf = __expf(-REGINV * c);
            hk[b] = __float2half(kf);
            hc[b] = __float2half(c);
            tr[tx * 4 + b][ty * 4 + a] = hk[b];
        }
        *(uint2*)&g_K[(size_t)i * NP + j0 + tx * 4] = *(const uint2*)hk;
        *(uint2*)&g_C[(size_t)i * NP + j0 + tx * 4] = *(const uint2*)hc;
    }
    __syncthreads();
    // KT write: 64 rows x 16 uint2 = 1024 uint2, 4 per thread, coalesced
#pragma unroll
    for (int q = 0; q < 4; q++) {
        int idx = tid + q * 256;
        int jj = idx >> 4;
        int ii = (idx & 15) * 4;
        *(uint2*)&g_KT[(size_t)(j0 + jj) * NP + i0 + ii] = *(const uint2*)&tr[jj][ii];
    }
}

// ---------------- u := 1 -------------------------------------------------
__global__ void initu_k() {
    g_u[blockIdx.x * 256 + threadIdx.x] = 1.0f;
}

// ---------------- fused matvec + reciprocal ------------------------------
// dir==0:  v[j] = MUV / (dot(KT[j], u) + EPS)
// dir==1:  u[i] = MUV / (dot(K [i], v) + EPS)
__global__ void matvec_k(int dir) {
    const __half* M = dir ? g_K : g_KT;
    const float*  x = dir ? g_v : g_u;
    float*        y = dir ? g_u : g_v;

    int w    = (blockIdx.x * blockDim.x + threadIdx.x) >> 5;
    int lane = threadIdx.x & 31;
    int r0 = w * 2, r1 = r0 + 1;
    const __half* p0 = M + (size_t)r0 * NP;
    const __half* p1 = M + (size_t)r1 * NP;

    float a0 = 0.f, a1 = 0.f;
#pragma unroll 4
    for (int t = 0; t < 16; t++) {
        int c = t * 256 + lane * 8;
        float4 xa = __ldg((const float4*)(x + c));
        float4 xb = __ldg((const float4*)(x + c + 4));
        uint4 q0 = *(const uint4*)(p0 + c);
        uint4 q1 = *(const uint4*)(p1 + c);
        const __half2* h0 = (const __half2*)&q0;
        const __half2* h1 = (const __half2*)&q1;
        float2 f;
        f = __half22float2(h0[0]); a0 += f.x * xa.x + f.y * xa.y;
        f = __half22float2(h0[1]); a0 += f.x * xa.z + f.y * xa.w;
        f = __half22float2(h0[2]); a0 += f.x * xb.x + f.y * xb.y;
        f = __half22float2(h0[3]); a0 += f.x * xb.z + f.y * xb.w;
        f = __half22float2(h1[0]); a1 += f.x * xa.x + f.y * xa.y;
        f = __half22float2(h1[1]); a1 += f.x * xa.z + f.y * xa.w;
        f = __half22float2(h1[2]); a1 += f.x * xb.x + f.y * xb.y;
        f = __half22float2(h1[3]); a1 += f.x * xb.z + f.y * xb.w;
    }
    a0 = wsum(a0);
    a1 = wsum(a1);
    if (lane == 0) {
        y[r0] = MUV / (a0 + EPSV);
        y[r1] = MUV / (a1 + EPSV);
    }
}

// ---------------- loss partials: sum_j u_i K_ij C_ij v_j -----------------
__global__ void loss_k() {
    __shared__ float sp[8];
    int w    = (blockIdx.x * blockDim.x + threadIdx.x) >> 5;  // row i
    int lane = threadIdx.x & 31;
    const __half* pk = g_K + (size_t)w * NP;
    const __half* pc = g_C + (size_t)w * NP;

    float s = 0.f;
#pragma unroll 4
    for (int t = 0; t < 16; t++) {
        int c = t * 256 + lane * 8;
        float4 va = __ldg((const float4*)(g_v + c));
        float4 vb = __ldg((const float4*)(g_v + c + 4));
        uint4 qk = *(const uint4*)(pk + c);
        uint4 qc = *(const uint4*)(pc + c);
        const __half2* hk = (const __half2*)&qk;
        const __half2* hc = (const __half2*)&qc;
        float2 fk, fc;
        fk = __half22float2(hk[0]); fc = __half22float2(hc[0]);
        s += fk.x * fc.x * va.x + fk.y * fc.y * va.y;
        fk = __half22float2(hk[1]); fc = __half22float2(hc[1]);
        s += fk.x * fc.x * va.z + fk.y * fc.y * va.w;
        fk = __half22float2(hk[2]); fc = __half22float2(hc[2]);
        s += fk.x * fc.x * vb.x + fk.y * fc.y * vb.y;
        fk = __half22float2(hk[3]); fc = __half22float2(hc[3]);
        s += fk.x * fc.x * vb.z + fk.y * fc.y * vb.w;
    }
    s = wsum(s);
    if (lane == 0) sp[threadIdx.x >> 5] = s * __ldg(g_u + w);
    __syncthreads();
    if (threadIdx.x == 0) {
        float b = 0.f;
#pragma unroll
        for (int q = 0; q < 8; q++) b += sp[q];
        g_part[blockIdx.x] = b;
    }
}

// ---------------- deterministic 512-way reduce, accumulate ---------------
__global__ void reduce_part_k() {
    __shared__ float sm[16];
    int tid = threadIdx.x;                    // 512 threads
    float v = g_part[tid];
    v = wsum(v);
    if ((tid & 31) == 0) sm[tid >> 5] = v;
    __syncthreads();
    if (tid < 32) {
        float b = (tid < 16) ? sm[tid] : 0.f;
        b = wsum(b);
        if (tid == 0) g_result += b;
    }
}

__global__ void fin_k(float* out) {
    out[0] = g_result * (1.0f / 3.0f);
}

// ---------------- launch -------------------------------------------------
extern "C" void kernel_launch(void* const* d_in, const int* in_sizes, int n_in,
                              void* d_out, int out_size) {
    const float* z0 = (const float*)d_in[0];
    const float* z1 = (const float*)d_in[1];
    const float* z2 = (const float*)d_in[2];
    float* out = (float*)d_out;

    norms_k<<<1536, 256>>>(z0, z1, z2);

    const float* Xs[3] = { z0, z0, z1 };
    const float* Ys[3] = { z1, z2, z2 };
    const int    xi[3] = { 0, 0, 1 };
    const int    yi[3] = { 1, 2, 2 };

    for (int p = 0; p < 3; p++) {
        gemm_expK_k<<<4096, 256>>>(Xs[p], Ys[p], xi[p], yi[p]);
        initu_k<<<16, 256>>>();
        for (int it = 0; it < NITER; it++) {
            matvec_k<<<256, 256>>>(0);   // v = nu/(KT u + eps)
            matvec_k<<<256, 256>>>(1);   // u = mu/(K v + eps)
        }
        loss_k<<<512, 256>>>();
        reduce_part_k<<<1, 512>>>();
    }
    fin_k<<<1, 1>>>(out);
}